// round 8
// baseline (speedup 1.0000x reference)
#include <cuda_runtime.h>

#define D_MODEL 128
#define D_EDGE  64
#define NB      4
#define NN      50000
#define BN      (NB*NN)          // 200000
#define BNP     200064           // BN padded to multiple of 128 (1563*128)
#define NE      600000

// ---------------- scratch (static device globals; no allocation allowed) ---
__device__ __align__(16) float g_wqa[D_MODEL];
__device__ __align__(16) float g_wka[D_MODEL];
__device__ __align__(16) float g_wewa[D_EDGE];
__device__ float g_cb;        // (bq+bk+bew)·Wa
__device__ __align__(16) float g_qa[BN];
__device__ __align__(16) float g_ka[BN];
__device__ __align__(16) float g_att_exp[NE];
__device__ __align__(16) float g_att_sum[BN];
__device__ __align__(16) float g_aggX[(size_t)BNP * D_MODEL];   // sum alpha * x[dst]
__device__ __align__(16) float g_aggE[(size_t)BNP * D_EDGE];    // sum alpha * e_emb
__device__ __align__(16) float g_alphaSum[BNP];

__device__ __forceinline__ int clampi(int v, int hi) {
    v = v < 0 ? 0 : v;
    return v > hi ? hi : v;
}

// ---------------- K0: zero the accumulators -------------------------------
__global__ void zero_kernel() {
    size_t tid    = (size_t)blockIdx.x * blockDim.x + threadIdx.x;
    size_t stride = (size_t)gridDim.x * blockDim.x;
    float4 z = make_float4(0.f, 0.f, 0.f, 0.f);
    float4* pX = (float4*)g_aggX;
    for (size_t i = tid; i < (size_t)BNP * D_MODEL / 4; i += stride) pX[i] = z;
    float4* pE = (float4*)g_aggE;
    for (size_t i = tid; i < (size_t)BNP * D_EDGE / 4; i += stride) pE[i] = z;
    for (size_t i = tid; i < BNP; i += stride) g_alphaSum[i] = 0.f;
    for (size_t i = tid; i < BN;  i += stride) g_att_sum[i]  = 0.f;
}

// ---------------- K1: fold Wa into the projection weights -----------------
__global__ void prep_kernel(const float* __restrict__ Wq, const float* __restrict__ Wk,
                            const float* __restrict__ Wew,
                            const float* __restrict__ bq, const float* __restrict__ bk,
                            const float* __restrict__ bew,
                            const float* __restrict__ Wa) {
    int i = threadIdx.x;
    float s1 = 0.f, s2 = 0.f;
    #pragma unroll 8
    for (int j = 0; j < D_MODEL; j++) {
        float w = Wa[j];
        s1 += Wq[i * D_MODEL + j] * w;
        s2 += Wk[i * D_MODEL + j] * w;
    }
    g_wqa[i] = s1;
    g_wka[i] = s2;
    if (i < D_EDGE) {
        float s3 = 0.f;
        #pragma unroll 8
        for (int j = 0; j < D_MODEL; j++) s3 += Wew[i * D_MODEL + j] * Wa[j];
        g_wewa[i] = s3;
    }
    if (i == 0) {
        float c = 0.f;
        for (int j = 0; j < D_MODEL; j++) c += (bq[j] + bk[j] + bew[j]) * Wa[j];
        g_cb = c;
    }
}

// ---------------- K2: per-node attention scalars qa, ka -------------------
__global__ void node_dot_kernel(const float* __restrict__ x) {
    int warp = (blockIdx.x * blockDim.x + threadIdx.x) >> 5;
    int lane = threadIdx.x & 31;
    if (warp >= BN) return;
    float4 v = ((const float4*)(x + (size_t)warp * D_MODEL))[lane];
    float4 a = ((const float4*)g_wqa)[lane];
    float4 b = ((const float4*)g_wka)[lane];
    float s1 = v.x * a.x + v.y * a.y + v.z * a.z + v.w * a.w;
    float s2 = v.x * b.x + v.y * b.y + v.z * b.z + v.w * b.w;
    #pragma unroll
    for (int off = 16; off; off >>= 1) {
        s1 += __shfl_down_sync(0xffffffffu, s1, off);
        s2 += __shfl_down_sync(0xffffffffu, s2, off);
    }
    if (lane == 0) { g_qa[warp] = s1; g_ka[warp] = s2; }
}

// ---------------- K3: edge logits + segment-sum of exp --------------------
// edge_index is int32, shape (2, E): src = ei[e], dst = ei[NE + e].
__global__ void edge_logit_kernel(const float* __restrict__ e_emb,
                                  const int* __restrict__ ei,
                                  const int* __restrict__ bi) {
    int e    = (blockIdx.x * blockDim.x + threadIdx.x) >> 5;
    int lane = threadIdx.x & 31;
    if (e >= NE) return;
    float2 ev = ((const float2*)(e_emb + (size_t)e * D_EDGE))[lane];
    float2 w  = ((const float2*)g_wewa)[lane];
    float s = ev.x * w.x + ev.y * w.y;
    #pragma unroll
    for (int off = 16; off; off >>= 1) s += __shfl_down_sync(0xffffffffu, s, off);
    if (lane == 0) {
        int src = clampi(ei[e],      NN - 1);
        int dst = clampi(ei[NE + e], NN - 1);
        int b   = clampi(bi[e],      NB - 1);
        int g   = b * NN + dst;
        // scale = 1/sqrt(d_head) = 1/sqrt(128/8) = 0.25
        float logit = (g_qa[b * NN + src] + g_ka[g] + s + g_cb) * 0.25f;
        float ex = expf(logit);
        g_att_exp[e] = ex;
        atomicAdd(&g_att_sum[g], ex);
    }
}

// ---------------- K4: scatter alpha-weighted x[dst] and e_emb into src ----
__global__ void scatter_kernel(const float* __restrict__ x,
                               const float* __restrict__ e_emb,
                               const int* __restrict__ ei,
                               const int* __restrict__ bi) {
    int e    = (blockIdx.x * blockDim.x + threadIdx.x) >> 5;
    int lane = threadIdx.x & 31;
    if (e >= NE) return;
    int src = clampi(ei[e],      NN - 1);
    int dst = clampi(ei[NE + e], NN - 1);
    int b   = clampi(bi[e],      NB - 1);
    float alpha = 0.f;
    if (lane == 0) {
        int g = b * NN + dst;
        alpha = g_att_exp[e] / (g_att_sum[g] + 1e-9f);
    }
    alpha = __shfl_sync(0xffffffffu, alpha, 0);

    int osrc = b * NN + src;
    // 128-dim: alpha * x[b, dst]
    float4 xv = ((const float4*)(x + (size_t)(b * NN + dst) * D_MODEL))[lane];
    float* ax = g_aggX + (size_t)osrc * D_MODEL + lane * 4;
    atomicAdd(ax + 0, alpha * xv.x);
    atomicAdd(ax + 1, alpha * xv.y);
    atomicAdd(ax + 2, alpha * xv.z);
    atomicAdd(ax + 3, alpha * xv.w);
    // 64-dim: alpha * e_emb[e]
    float2 ev = ((const float2*)(e_emb + (size_t)e * D_EDGE))[lane];
    float* ae = g_aggE + (size_t)osrc * D_EDGE + lane * 2;
    atomicAdd(ae + 0, alpha * ev.x);
    atomicAdd(ae + 1, alpha * ev.y);
    if (lane == 0) atomicAdd(&g_alphaSum[osrc], alpha);
}

// ---------------- K5: fused output GEMM  out = [aggX|aggE]@[Wv;Wev] + as*(bv+bev)
#define TM 128
#define TN 128
#define TK 8
__global__ __launch_bounds__(256) void out_gemm_kernel(
        const float* __restrict__ Wv, const float* __restrict__ Wev,
        const float* __restrict__ bv, const float* __restrict__ bev,
        float* __restrict__ out) {
    __shared__ __align__(16) float As[TK][TM];
    __shared__ __align__(16) float Bs[TK][TN];
    int m0  = blockIdx.x * TM;
    int tid = threadIdx.x;
    int tr  = (tid >> 4) << 3;  // row base within tile (0..120)
    int tc  = (tid & 15) << 3;  // col base within tile (0..120)

    float acc[8][8];
    #pragma unroll
    for (int i = 0; i < 8; i++)
        #pragma unroll
        for (int j = 0; j < 8; j++) acc[i][j] = 0.f;

    // Phase 1: k in [0, 128) -> A from g_aggX, B from Wv
    // Phase 2: k in [128, 192) -> A from g_aggE, B from Wev
    for (int k0 = 0; k0 < (D_MODEL + D_EDGE); k0 += TK) {
        // A tile: [kk][row] transposed
        {
            int r  = tid >> 1;
            int kk = (tid & 1) << 2;
            int k  = k0 + kk;
            size_t m = (size_t)(m0 + r);
            float4 av;
            if (k < D_MODEL) av = *(const float4*)(g_aggX + m * D_MODEL + k);
            else             av = *(const float4*)(g_aggE + m * D_EDGE + (k - D_MODEL));
            As[kk + 0][r] = av.x;
            As[kk + 1][r] = av.y;
            As[kk + 2][r] = av.z;
            As[kk + 3][r] = av.w;
        }
        // B tile: concat weight rows
        {
            int kk = tid >> 5;
            int c  = (tid & 31) << 2;
            int kb = k0 + kk;
            float4 bvv;
            if (kb < D_MODEL) bvv = *(const float4*)(Wv  + (size_t)kb * D_MODEL + c);
            else              bvv = *(const float4*)(Wev + (size_t)(kb - D_MODEL) * D_MODEL + c);
            *(float4*)&Bs[kk][c] = bvv;
        }
        __syncthreads();
        #pragma unroll
        for (int kk = 0; kk < TK; kk++) {
            float4 a0 = *(const float4*)&As[kk][tr];
            float4 a1 = *(const float4*)&As[kk][tr + 4];
            float4 b0 = *(const float4*)&Bs[kk][tc];
            float4 b1 = *(const float4*)&Bs[kk][tc + 4];
            float aa[8] = {a0.x, a0.y, a0.z, a0.w, a1.x, a1.y, a1.z, a1.w};
            float bb[8] = {b0.x, b0.y, b0.z, b0.w, b1.x, b1.y, b1.z, b1.w};
            #pragma unroll
            for (int i = 0; i < 8; i++)
                #pragma unroll
                for (int j = 0; j < 8; j++)
                    acc[i][j] = fmaf(aa[i], bb[j], acc[i][j]);
        }
        __syncthreads();
    }

    // epilogue: + alphaSum * (bv + bev), guarded stores
    float bias[8];
    #pragma unroll
    for (int j = 0; j < 8; j++) bias[j] = bv[tc + j] + bev[tc + j];
    #pragma unroll
    for (int i = 0; i < 8; i++) {
        int m = m0 + tr + i;
        if (m < BN) {
            float as = g_alphaSum[m];
            float o[8];
            #pragma unroll
            for (int j = 0; j < 8; j++) o[j] = acc[i][j] + as * bias[j];
            *(float4*)&out[(size_t)m * D_MODEL + tc]     = make_float4(o[0], o[1], o[2], o[3]);
            *(float4*)&out[(size_t)m * D_MODEL + tc + 4] = make_float4(o[4], o[5], o[6], o[7]);
        }
    }
}

// ---------------- launch ---------------------------------------------------
extern "C" void kernel_launch(void* const* d_in, const int* in_sizes, int n_in,
                              void* d_out, int out_size) {
    const float* x     = (const float*)d_in[0];
    const int*   ei    = (const int*)d_in[1];    // int32 (JAX default; no x64)
    const float* e_emb = (const float*)d_in[2];
    const int*   bi    = (const int*)d_in[3];    // int32

    // n_heads may or may not be materialized as an input buffer; detect it.
    int o = 4;
    if (n_in >= 16 && in_sizes[4] == 1) { o = 5; }

    const float* Wq  = (const float*)d_in[o + 0];
    const float* bq  = (const float*)d_in[o + 1];
    const float* Wk  = (const float*)d_in[o + 2];
    const float* bk  = (const float*)d_in[o + 3];
    const float* Wv  = (const float*)d_in[o + 4];
    const float* bv  = (const float*)d_in[o + 5];
    const float* Wew = (const float*)d_in[o + 6];
    const float* bew = (const float*)d_in[o + 7];
    const float* Wev = (const float*)d_in[o + 8];
    const float* bev = (const float*)d_in[o + 9];
    const float* Wa  = (const float*)d_in[o + 10];
    float* out = (float*)d_out;

    zero_kernel<<<4096, 256>>>();
    prep_kernel<<<1, 128>>>(Wq, Wk, Wew, bq, bk, bew, Wa);
    node_dot_kernel<<<(BN * 32 + 255) / 256, 256>>>(x);
    edge_logit_kernel<<<(NE * 32 + 255) / 256, 256>>>(e_emb, ei, bi);
    scatter_kernel<<<(NE * 32 + 255) / 256, 256>>>(x, e_emb, ei, bi);
    out_gemm_kernel<<<BNP / TM, 256>>>(Wv, Wev, bv, bev, out);
}

// round 13
// speedup vs baseline: 1.0201x; 1.0201x over previous
#include <cuda_runtime.h>

#define D_MODEL 128
#define D_EDGE  64
#define NB      4
#define NN      50000
#define BN      (NB*NN)          // 200000
#define BNP     200064           // BN padded to multiple of 128 (1563*128)
#define NE      600000

// ---------------- scratch (static device globals; no allocation allowed) ---
__device__ __align__(16) float g_wqa[D_MODEL];
__device__ __align__(16) float g_wka[D_MODEL];
__device__ __align__(16) float g_wewa[D_EDGE];
__device__ float g_cb;        // (bq+bk+bew)·Wa
__device__ __align__(16) float g_qa[BN];
__device__ __align__(16) float g_ka[BN];
__device__ __align__(16) float g_att_exp[NE];
__device__ __align__(16) float g_att_sum[BN];
__device__ __align__(16) float g_aggX[(size_t)BNP * D_MODEL];   // sum alpha * x[dst]
__device__ __align__(16) float g_aggE[(size_t)BNP * D_EDGE];    // sum alpha * e_emb
__device__ __align__(16) float g_alphaSum[BNP];

__device__ __forceinline__ int clampi(int v, int hi) {
    v = v < 0 ? 0 : v;
    return v > hi ? hi : v;
}

// ---------------- K0: zero the accumulators -------------------------------
__global__ void zero_kernel() {
    size_t tid    = (size_t)blockIdx.x * blockDim.x + threadIdx.x;
    size_t stride = (size_t)gridDim.x * blockDim.x;
    float4 z = make_float4(0.f, 0.f, 0.f, 0.f);
    float4* pX = (float4*)g_aggX;
    for (size_t i = tid; i < (size_t)BNP * D_MODEL / 4; i += stride) pX[i] = z;
    float4* pE = (float4*)g_aggE;
    for (size_t i = tid; i < (size_t)BNP * D_EDGE / 4; i += stride) pE[i] = z;
    for (size_t i = tid; i < BNP; i += stride) g_alphaSum[i] = 0.f;
    for (size_t i = tid; i < BN;  i += stride) g_att_sum[i]  = 0.f;
}

// ---------------- K1: fold Wa into the projection weights -----------------
__global__ void prep_kernel(const float* __restrict__ Wq, const float* __restrict__ Wk,
                            const float* __restrict__ Wew,
                            const float* __restrict__ bq, const float* __restrict__ bk,
                            const float* __restrict__ bew,
                            const float* __restrict__ Wa) {
    int i = threadIdx.x;
    float s1 = 0.f, s2 = 0.f;
    #pragma unroll 8
    for (int j = 0; j < D_MODEL; j++) {
        float w = Wa[j];
        s1 += Wq[i * D_MODEL + j] * w;
        s2 += Wk[i * D_MODEL + j] * w;
    }
    g_wqa[i] = s1;
    g_wka[i] = s2;
    if (i < D_EDGE) {
        float s3 = 0.f;
        #pragma unroll 8
        for (int j = 0; j < D_MODEL; j++) s3 += Wew[i * D_MODEL + j] * Wa[j];
        g_wewa[i] = s3;
    }
    if (i == 0) {
        float c = 0.f;
        for (int j = 0; j < D_MODEL; j++) c += (bq[j] + bk[j] + bew[j]) * Wa[j];
        g_cb = c;
    }
}

// ---------------- K2: per-node attention scalars qa, ka -------------------
__global__ void node_dot_kernel(const float* __restrict__ x) {
    int warp = (blockIdx.x * blockDim.x + threadIdx.x) >> 5;
    int lane = threadIdx.x & 31;
    if (warp >= BN) return;
    float4 v = ((const float4*)(x + (size_t)warp * D_MODEL))[lane];
    float4 a = ((const float4*)g_wqa)[lane];
    float4 b = ((const float4*)g_wka)[lane];
    float s1 = v.x * a.x + v.y * a.y + v.z * a.z + v.w * a.w;
    float s2 = v.x * b.x + v.y * b.y + v.z * b.z + v.w * b.w;
    #pragma unroll
    for (int off = 16; off; off >>= 1) {
        s1 += __shfl_down_sync(0xffffffffu, s1, off);
        s2 += __shfl_down_sync(0xffffffffu, s2, off);
    }
    if (lane == 0) { g_qa[warp] = s1; g_ka[warp] = s2; }
}

// ---------------- K3: edge logits + segment-sum of exp --------------------
// edge_index is int32, shape (2, E): src = ei[e], dst = ei[NE + e].
__global__ void edge_logit_kernel(const float* __restrict__ e_emb,
                                  const int* __restrict__ ei,
                                  const int* __restrict__ bi) {
    int e    = (blockIdx.x * blockDim.x + threadIdx.x) >> 5;
    int lane = threadIdx.x & 31;
    if (e >= NE) return;
    float2 ev = ((const float2*)(e_emb + (size_t)e * D_EDGE))[lane];
    float2 w  = ((const float2*)g_wewa)[lane];
    float s = ev.x * w.x + ev.y * w.y;
    #pragma unroll
    for (int off = 16; off; off >>= 1) s += __shfl_down_sync(0xffffffffu, s, off);
    if (lane == 0) {
        int src = clampi(ei[e],      NN - 1);
        int dst = clampi(ei[NE + e], NN - 1);
        int b   = clampi(bi[e],      NB - 1);
        int g   = b * NN + dst;
        // scale = 1/sqrt(d_head) = 1/sqrt(128/8) = 0.25
        float logit = (g_qa[b * NN + src] + g_ka[g] + s + g_cb) * 0.25f;
        float ex = expf(logit);
        g_att_exp[e] = ex;
        atomicAdd(&g_att_sum[g], ex);
    }
}

// ---------------- K4: scatter alpha-weighted x[dst] and e_emb into src ----
__global__ void scatter_kernel(const float* __restrict__ x,
                               const float* __restrict__ e_emb,
                               const int* __restrict__ ei,
                               const int* __restrict__ bi) {
    int e    = (blockIdx.x * blockDim.x + threadIdx.x) >> 5;
    int lane = threadIdx.x & 31;
    if (e >= NE) return;
    int src = clampi(ei[e],      NN - 1);
    int dst = clampi(ei[NE + e], NN - 1);
    int b   = clampi(bi[e],      NB - 1);
    float alpha = 0.f;
    if (lane == 0) {
        int g = b * NN + dst;
        alpha = g_att_exp[e] / (g_att_sum[g] + 1e-9f);
    }
    alpha = __shfl_sync(0xffffffffu, alpha, 0);

    int osrc = b * NN + src;
    // 128-dim: alpha * x[b, dst]
    float4 xv = ((const float4*)(x + (size_t)(b * NN + dst) * D_MODEL))[lane];
    float* ax = g_aggX + (size_t)osrc * D_MODEL + lane * 4;
    atomicAdd(ax + 0, alpha * xv.x);
    atomicAdd(ax + 1, alpha * xv.y);
    atomicAdd(ax + 2, alpha * xv.z);
    atomicAdd(ax + 3, alpha * xv.w);
    // 64-dim: alpha * e_emb[e]
    float2 ev = ((const float2*)(e_emb + (size_t)e * D_EDGE))[lane];
    float* ae = g_aggE + (size_t)osrc * D_EDGE + lane * 2;
    atomicAdd(ae + 0, alpha * ev.x);
    atomicAdd(ae + 1, alpha * ev.y);
    if (lane == 0) atomicAdd(&g_alphaSum[osrc], alpha);
}

// ---------------- K5: fused output GEMM  out = [aggX|aggE]@[Wv;Wev] + as*(bv+bev)
#define TM 128
#define TN 128
#define TK 8
__global__ __launch_bounds__(256) void out_gemm_kernel(
        const float* __restrict__ Wv, const float* __restrict__ Wev,
        const float* __restrict__ bv, const float* __restrict__ bev,
        float* __restrict__ out) {
    __shared__ __align__(16) float As[TK][TM];
    __shared__ __align__(16) float Bs[TK][TN];
    int m0  = blockIdx.x * TM;
    int tid = threadIdx.x;
    int tr  = (tid >> 4) << 3;  // row base within tile (0..120)
    int tc  = (tid & 15) << 3;  // col base within tile (0..120)

    float acc[8][8];
    #pragma unroll
    for (int i = 0; i < 8; i++)
        #pragma unroll
        for (int j = 0; j < 8; j++) acc[i][j] = 0.f;

    // Phase 1: k in [0, 128) -> A from g_aggX, B from Wv
    // Phase 2: k in [128, 192) -> A from g_aggE, B from Wev
    for (int k0 = 0; k0 < (D_MODEL + D_EDGE); k0 += TK) {
        // A tile: [kk][row] transposed
        {
            int r  = tid >> 1;
            int kk = (tid & 1) << 2;
            int k  = k0 + kk;
            size_t m = (size_t)(m0 + r);
            float4 av;
            if (k < D_MODEL) av = *(const float4*)(g_aggX + m * D_MODEL + k);
            else             av = *(const float4*)(g_aggE + m * D_EDGE + (k - D_MODEL));
            As[kk + 0][r] = av.x;
            As[kk + 1][r] = av.y;
            As[kk + 2][r] = av.z;
            As[kk + 3][r] = av.w;
        }
        // B tile: concat weight rows
        {
            int kk = tid >> 5;
            int c  = (tid & 31) << 2;
            int kb = k0 + kk;
            float4 bvv;
            if (kb < D_MODEL) bvv = *(const float4*)(Wv  + (size_t)kb * D_MODEL + c);
            else              bvv = *(const float4*)(Wev + (size_t)(kb - D_MODEL) * D_MODEL + c);
            *(float4*)&Bs[kk][c] = bvv;
        }
        __syncthreads();
        #pragma unroll
        for (int kk = 0; kk < TK; kk++) {
            float4 a0 = *(const float4*)&As[kk][tr];
            float4 a1 = *(const float4*)&As[kk][tr + 4];
            float4 b0 = *(const float4*)&Bs[kk][tc];
            float4 b1 = *(const float4*)&Bs[kk][tc + 4];
            float aa[8] = {a0.x, a0.y, a0.z, a0.w, a1.x, a1.y, a1.z, a1.w};
            float bb[8] = {b0.x, b0.y, b0.z, b0.w, b1.x, b1.y, b1.z, b1.w};
            #pragma unroll
            for (int i = 0; i < 8; i++)
                #pragma unroll
                for (int j = 0; j < 8; j++)
                    acc[i][j] = fmaf(aa[i], bb[j], acc[i][j]);
        }
        __syncthreads();
    }

    // epilogue: + alphaSum * (bv + bev), guarded stores
    float bias[8];
    #pragma unroll
    for (int j = 0; j < 8; j++) bias[j] = bv[tc + j] + bev[tc + j];
    #pragma unroll
    for (int i = 0; i < 8; i++) {
        int m = m0 + tr + i;
        if (m < BN) {
            float as = g_alphaSum[m];
            float o[8];
            #pragma unroll
            for (int j = 0; j < 8; j++) o[j] = acc[i][j] + as * bias[j];
            *(float4*)&out[(size_t)m * D_MODEL + tc]     = make_float4(o[0], o[1], o[2], o[3]);
            *(float4*)&out[(size_t)m * D_MODEL + tc + 4] = make_float4(o[4], o[5], o[6], o[7]);
        }
    }
}

// ---------------- launch ---------------------------------------------------
extern "C" void kernel_launch(void* const* d_in, const int* in_sizes, int n_in,
                              void* d_out, int out_size) {
    const float* x     = (const float*)d_in[0];
    const int*   ei    = (const int*)d_in[1];    // int32 (JAX default; no x64)
    const float* e_emb = (const float*)d_in[2];
    const int*   bi    = (const int*)d_in[3];    // int32

    // n_heads may or may not be materialized as an input buffer; detect it.
    int o = 4;
    if (n_in >= 16 && in_sizes[4] == 1) { o = 5; }

    const float* Wq  = (const float*)d_in[o + 0];
    const float* bq  = (const float*)d_in[o + 1];
    const float* Wk  = (const float*)d_in[o + 2];
    const float* bk  = (const float*)d_in[o + 3];
    const float* Wv  = (const float*)d_in[o + 4];
    const float* bv  = (const float*)d_in[o + 5];
    const float* Wew = (const float*)d_in[o + 6];
    const float* bew = (const float*)d_in[o + 7];
    const float* Wev = (const float*)d_in[o + 8];
    const float* bev = (const float*)d_in[o + 9];
    const float* Wa  = (const float*)d_in[o + 10];
    float* out = (float*)d_out;

    zero_kernel<<<4096, 256>>>();
    prep_kernel<<<1, 128>>>(Wq, Wk, Wew, bq, bk, bew, Wa);
    node_dot_kernel<<<(BN * 32 + 255) / 256, 256>>>(x);
    edge_logit_kernel<<<(NE * 32 + 255) / 256, 256>>>(e_emb, ei, bi);
    scatter_kernel<<<(NE * 32 + 255) / 256, 256>>>(x, e_emb, ei, bi);
    out_gemm_kernel<<<BNP / TM, 256>>>(Wv, Wev, bv, bev, out);
}

// round 14
// speedup vs baseline: 1.3009x; 1.2752x over previous
#include <cuda_runtime.h>

#define D_MODEL 128
#define D_EDGE  64
#define NB      4
#define NN      50000
#define BN      (NB*NN)          // 200000
#define BNP     200064           // BN padded to multiple of 128 (1563*128)
#define NE      600000

// ---------------- scratch (static device globals; no allocation allowed) ---
__device__ __align__(16) float g_wqa[D_MODEL];
__device__ __align__(16) float g_wka[D_MODEL];
__device__ __align__(16) float g_wewa[D_EDGE];
__device__ float g_cb;        // (bq+bk+bew)·Wa
__device__ __align__(16) float g_qa[BN];
__device__ __align__(16) float g_ka[BN];
__device__ __align__(16) float g_edot[NE];     // e_emb[e] . wewa
__device__ __align__(16) float g_att_exp[NE];  // exp(logit), later overwritten by alpha
__device__ __align__(16) float g_att_sum[BN];
__device__ __align__(16) float g_aggX[(size_t)BNP * D_MODEL];   // sum alpha * x[dst]
__device__ __align__(16) float g_aggE[(size_t)BNP * D_EDGE];    // sum alpha * e_emb
__device__ __align__(16) float g_alphaSum[BNP];

__device__ __forceinline__ int clampi(int v, int hi) {
    v = v < 0 ? 0 : v;
    return v > hi ? hi : v;
}

// ---------------- packed f32x2 helpers (full-rate fp32 on sm_103a) --------
__device__ __forceinline__ void fma2(unsigned long long& d,
                                     unsigned long long a,
                                     unsigned long long b) {
    asm("fma.rn.f32x2 %0, %1, %2, %0;" : "+l"(d) : "l"(a), "l"(b));
}
__device__ __forceinline__ unsigned long long pack2(float x, float y) {
    unsigned long long r;
    asm("mov.b64 %0, {%1, %2};" : "=l"(r) : "f"(x), "f"(y));
    return r;
}
__device__ __forceinline__ void unpack2(unsigned long long v, float& x, float& y) {
    asm("mov.b64 {%0, %1}, %2;" : "=f"(x), "=f"(y) : "l"(v));
}

// ---------------- K0: zero the accumulators -------------------------------
__global__ void zero_kernel() {
    size_t tid    = (size_t)blockIdx.x * blockDim.x + threadIdx.x;
    size_t stride = (size_t)gridDim.x * blockDim.x;
    float4 z = make_float4(0.f, 0.f, 0.f, 0.f);
    float4* pX = (float4*)g_aggX;
    for (size_t i = tid; i < (size_t)BNP * D_MODEL / 4; i += stride) pX[i] = z;
    float4* pE = (float4*)g_aggE;
    for (size_t i = tid; i < (size_t)BNP * D_EDGE / 4; i += stride) pE[i] = z;
    for (size_t i = tid; i < BNP; i += stride) g_alphaSum[i] = 0.f;
    for (size_t i = tid; i < BN;  i += stride) g_att_sum[i]  = 0.f;
}

// ---------------- K1: fold Wa into the projection weights -----------------
__global__ void prep_kernel(const float* __restrict__ Wq, const float* __restrict__ Wk,
                            const float* __restrict__ Wew,
                            const float* __restrict__ bq, const float* __restrict__ bk,
                            const float* __restrict__ bew,
                            const float* __restrict__ Wa) {
    int i = threadIdx.x;
    float s1 = 0.f, s2 = 0.f;
    #pragma unroll 8
    for (int j = 0; j < D_MODEL; j++) {
        float w = Wa[j];
        s1 += Wq[i * D_MODEL + j] * w;
        s2 += Wk[i * D_MODEL + j] * w;
    }
    g_wqa[i] = s1;
    g_wka[i] = s2;
    if (i < D_EDGE) {
        float s3 = 0.f;
        #pragma unroll 8
        for (int j = 0; j < D_MODEL; j++) s3 += Wew[i * D_MODEL + j] * Wa[j];
        g_wewa[i] = s3;
    }
    if (i == 0) {
        float c = 0.f;
        for (int j = 0; j < D_MODEL; j++) c += (bq[j] + bk[j] + bew[j]) * Wa[j];
        g_cb = c;
    }
}

// ---------------- K2: per-node attention scalars qa, ka -------------------
__global__ void node_dot_kernel(const float* __restrict__ x) {
    int warp = (blockIdx.x * blockDim.x + threadIdx.x) >> 5;
    int lane = threadIdx.x & 31;
    if (warp >= BN) return;
    float4 v = ((const float4*)(x + (size_t)warp * D_MODEL))[lane];
    float4 a = ((const float4*)g_wqa)[lane];
    float4 b = ((const float4*)g_wka)[lane];
    float s1 = v.x * a.x + v.y * a.y + v.z * a.z + v.w * a.w;
    float s2 = v.x * b.x + v.y * b.y + v.z * b.z + v.w * b.w;
    #pragma unroll
    for (int off = 16; off; off >>= 1) {
        s1 += __shfl_down_sync(0xffffffffu, s1, off);
        s2 += __shfl_down_sync(0xffffffffu, s2, off);
    }
    if (lane == 0) { g_qa[warp] = s1; g_ka[warp] = s2; }
}

// ---------------- K3a: streaming edge dot  g_edot[e] = e_emb[e].wewa -------
// 2 edges per warp, 16 lanes x float4 per edge: fully coalesced 256B/edge.
__global__ void edge_dot_kernel(const float* __restrict__ e_emb) {
    int warp = (blockIdx.x * blockDim.x + threadIdx.x) >> 5;
    int lane = threadIdx.x & 31;
    int e    = warp * 2 + (lane >> 4);
    int l16  = lane & 15;
    if (e >= NE) return;
    float4 v = ((const float4*)e_emb)[(size_t)e * (D_EDGE / 4) + l16];
    float4 w = ((const float4*)g_wewa)[l16];
    float s = v.x * w.x + v.y * w.y + v.z * w.z + v.w * w.w;
    #pragma unroll
    for (int off = 8; off; off >>= 1) s += __shfl_down_sync(0xffffffffu, s, off, 16);
    if (l16 == 0) g_edot[e] = s;
}

// ---------------- K3b: per-edge scalar logits + segment-sum of exp --------
__global__ void edge_logit_kernel(const int* __restrict__ ei,
                                  const int* __restrict__ bi) {
    int e = blockIdx.x * blockDim.x + threadIdx.x;
    if (e >= NE) return;
    int src = clampi(ei[e],      NN - 1);
    int dst = clampi(ei[NE + e], NN - 1);
    int b   = clampi(bi[e],      NB - 1);
    int g   = b * NN + dst;
    // scale = 1/sqrt(d_head) = 1/sqrt(128/8) = 0.25
    float logit = (g_qa[b * NN + src] + g_ka[g] + g_edot[e] + g_cb) * 0.25f;
    float ex = expf(logit);
    g_att_exp[e] = ex;
    atomicAdd(&g_att_sum[g], ex);
}

// ---------------- K3c: alpha[e] = exp / (sum + eps)  (in place) -----------
__global__ void alpha_kernel(const int* __restrict__ ei,
                             const int* __restrict__ bi) {
    int e = blockIdx.x * blockDim.x + threadIdx.x;
    if (e >= NE) return;
    int dst = clampi(ei[NE + e], NN - 1);
    int b   = clampi(bi[e],      NB - 1);
    int g   = b * NN + dst;
    g_att_exp[e] = g_att_exp[e] / (g_att_sum[g] + 1e-9f);
}

// ---------------- K4: scatter alpha-weighted x[dst] and e_emb into src ----
// warp per edge; vector RED.128 atomics (sm_90+ float4 atomicAdd).
__global__ void scatter_kernel(const float* __restrict__ x,
                               const float* __restrict__ e_emb,
                               const int* __restrict__ ei,
                               const int* __restrict__ bi) {
    int e    = (blockIdx.x * blockDim.x + threadIdx.x) >> 5;
    int lane = threadIdx.x & 31;
    if (e >= NE) return;
    int src = clampi(ei[e],      NN - 1);
    int dst = clampi(ei[NE + e], NN - 1);
    int b   = clampi(bi[e],      NB - 1);
    float alpha = g_att_exp[e];          // broadcast load (same address all lanes)
    int osrc = b * NN + src;

    // 128-dim: alpha * x[b, dst] -> aggX[osrc]
    float4 xv = ((const float4*)(x + (size_t)(b * NN + dst) * D_MODEL))[lane];
    atomicAdd((float4*)(g_aggX + (size_t)osrc * D_MODEL + lane * 4),
              make_float4(alpha * xv.x, alpha * xv.y, alpha * xv.z, alpha * xv.w));

    // 64-dim: alpha * e_emb[e] -> aggE[osrc]  (lanes 0-15)
    if (lane < 16) {
        float4 ev = ((const float4*)e_emb)[(size_t)e * (D_EDGE / 4) + lane];
        atomicAdd((float4*)(g_aggE + (size_t)osrc * D_EDGE + lane * 4),
                  make_float4(alpha * ev.x, alpha * ev.y, alpha * ev.z, alpha * ev.w));
    } else if (lane == 16) {
        atomicAdd(&g_alphaSum[osrc], alpha);
    }
}

// ---------------- K5: fused output GEMM  out = [aggX|aggE]@[Wv;Wev] + as*(bv+bev)
#define TM 128
#define TN 128
#define TK 8
__global__ __launch_bounds__(256) void out_gemm_kernel(
        const float* __restrict__ Wv, const float* __restrict__ Wev,
        const float* __restrict__ bv, const float* __restrict__ bev,
        float* __restrict__ out) {
    __shared__ __align__(16) float As[TK][TM];
    __shared__ __align__(16) float Bs[TK][TN];
    int m0  = blockIdx.x * TM;
    int tid = threadIdx.x;
    int tr  = (tid >> 4) << 3;  // row base within tile (0..120)
    int tc  = (tid & 15) << 3;  // col base within tile (0..120)

    unsigned long long acc2[8][4];
    #pragma unroll
    for (int i = 0; i < 8; i++)
        #pragma unroll
        for (int j = 0; j < 4; j++) acc2[i][j] = 0ull;

    for (int k0 = 0; k0 < (D_MODEL + D_EDGE); k0 += TK) {
        // A tile: [kk][row] transposed
        {
            int r  = tid >> 1;
            int kk = (tid & 1) << 2;
            int k  = k0 + kk;
            size_t m = (size_t)(m0 + r);
            float4 av;
            if (k < D_MODEL) av = *(const float4*)(g_aggX + m * D_MODEL + k);
            else             av = *(const float4*)(g_aggE + m * D_EDGE + (k - D_MODEL));
            As[kk + 0][r] = av.x;
            As[kk + 1][r] = av.y;
            As[kk + 2][r] = av.z;
            As[kk + 3][r] = av.w;
        }
        // B tile: concat weight rows
        {
            int kk = tid >> 5;
            int c  = (tid & 31) << 2;
            int kb = k0 + kk;
            float4 bvv;
            if (kb < D_MODEL) bvv = *(const float4*)(Wv  + (size_t)kb * D_MODEL + c);
            else              bvv = *(const float4*)(Wev + (size_t)(kb - D_MODEL) * D_MODEL + c);
            *(float4*)&Bs[kk][c] = bvv;
        }
        __syncthreads();
        #pragma unroll
        for (int kk = 0; kk < TK; kk++) {
            float4 a0 = *(const float4*)&As[kk][tr];
            float4 a1 = *(const float4*)&As[kk][tr + 4];
            ulonglong2 b0 = *(const ulonglong2*)&Bs[kk][tc];
            ulonglong2 b1 = *(const ulonglong2*)&Bs[kk][tc + 4];
            unsigned long long bb[4] = {b0.x, b0.y, b1.x, b1.y};
            float aa[8] = {a0.x, a0.y, a0.z, a0.w, a1.x, a1.y, a1.z, a1.w};
            #pragma unroll
            for (int i = 0; i < 8; i++) {
                unsigned long long ap = pack2(aa[i], aa[i]);
                #pragma unroll
                for (int j = 0; j < 4; j++) fma2(acc2[i][j], ap, bb[j]);
            }
        }
        __syncthreads();
    }

    // epilogue: + alphaSum * (bv + bev), guarded stores
    float bias[8];
    #pragma unroll
    for (int j = 0; j < 8; j++) bias[j] = bv[tc + j] + bev[tc + j];
    #pragma unroll
    for (int i = 0; i < 8; i++) {
        int m = m0 + tr + i;
        if (m < BN) {
            float as = g_alphaSum[m];
            float o[8];
            #pragma unroll
            for (int j = 0; j < 4; j++) unpack2(acc2[i][j], o[2 * j], o[2 * j + 1]);
            #pragma unroll
            for (int j = 0; j < 8; j++) o[j] += as * bias[j];
            *(float4*)&out[(size_t)m * D_MODEL + tc]     = make_float4(o[0], o[1], o[2], o[3]);
            *(float4*)&out[(size_t)m * D_MODEL + tc + 4] = make_float4(o[4], o[5], o[6], o[7]);
        }
    }
}

// ---------------- launch ---------------------------------------------------
extern "C" void kernel_launch(void* const* d_in, const int* in_sizes, int n_in,
                              void* d_out, int out_size) {
    const float* x     = (const float*)d_in[0];
    const int*   ei    = (const int*)d_in[1];    // int32 (JAX default; no x64)
    const float* e_emb = (const float*)d_in[2];
    const int*   bi    = (const int*)d_in[3];    // int32

    // n_heads may or may not be materialized as an input buffer; detect it.
    int o = 4;
    if (n_in >= 16 && in_sizes[4] == 1) { o = 5; }

    const float* Wq  = (const float*)d_in[o + 0];
    const float* bq  = (const float*)d_in[o + 1];
    const float* Wk  = (const float*)d_in[o + 2];
    const float* bk  = (const float*)d_in[o + 3];
    const float* Wv  = (const float*)d_in[o + 4];
    const float* bv  = (const float*)d_in[o + 5];
    const float* Wew = (const float*)d_in[o + 6];
    const float* bew = (const float*)d_in[o + 7];
    const float* Wev = (const float*)d_in[o + 8];
    const float* bev = (const float*)d_in[o + 9];
    const float* Wa  = (const float*)d_in[o + 10];
    float* out = (float*)d_out;

    zero_kernel<<<4096, 256>>>();
    prep_kernel<<<1, 128>>>(Wq, Wk, Wew, bq, bk, bew, Wa);
    node_dot_kernel<<<(BN * 32 + 255) / 256, 256>>>(x);
    edge_dot_kernel<<<(NE * 16 + 255) / 256, 256>>>(e_emb);
    edge_logit_kernel<<<(NE + 255) / 256, 256>>>(ei, bi);
    alpha_kernel<<<(NE + 255) / 256, 256>>>(ei, bi);
    scatter_kernel<<<(NE * 32 + 255) / 256, 256>>>(x, e_emb, ei, bi);
    out_gemm_kernel<<<BNP / TM, 256>>>(Wv, Wev, bv, bev, out);
}

// round 15
// speedup vs baseline: 1.4865x; 1.1427x over previous
#include <cuda_runtime.h>

#define D_MODEL 128
#define D_EDGE  64
#define NB      4
#define NN      50000
#define BN      (NB*NN)          // 200000
#define BNP     200064           // BN padded to multiple of 128
#define NE      600000
#define SCAN_N  200704           // 196 * 1024, scan-padded bin count
#define SCAN_B  196

// ---------------- scratch (static device globals; no allocation allowed) ---
__device__ __align__(16) float g_wqa[D_MODEL];
__device__ __align__(16) float g_wka[D_MODEL];
__device__ __align__(16) float g_wewa[D_EDGE];
__device__ float g_cb;
__device__ __align__(16) float g_qa[BN];
__device__ __align__(16) float g_ka[BN];
__device__ __align__(16) float g_edot[NE];     // e_emb[e] . wewa
__device__ __align__(16) float g_att_exp[NE];
__device__ __align__(16) float g_att_sum[BN];
__device__ __align__(16) int   g_count[SCAN_N];   // per-(b,src) degree, then reused
__device__ __align__(16) int   g_rank[NE];
__device__ __align__(16) int   g_off[SCAN_N];     // exclusive prefix
__device__ __align__(16) int   g_bsum[256];
__device__ __align__(16) int   g_boff[256];
__device__ __align__(16) int   g_s_dst[NE];       // sorted-by-src edge data
__device__ __align__(16) int   g_s_eid[NE];
__device__ __align__(16) float g_s_alpha[NE];
__device__ __align__(16) float g_aggX[(size_t)BNP * D_MODEL];  // stays 0 in pad rows
__device__ __align__(16) float g_aggE[(size_t)BNP * D_EDGE];
__device__ __align__(16) float g_alphaSum[BNP];

__device__ __forceinline__ int clampi(int v, int hi) {
    v = v < 0 ? 0 : v;
    return v > hi ? hi : v;
}

// ---------------- packed f32x2 helpers ------------------------------------
__device__ __forceinline__ void fma2(unsigned long long& d,
                                     unsigned long long a,
                                     unsigned long long b) {
    asm("fma.rn.f32x2 %0, %1, %2, %0;" : "+l"(d) : "l"(a), "l"(b));
}
__device__ __forceinline__ unsigned long long pack2(float x, float y) {
    unsigned long long r;
    asm("mov.b64 %0, {%1, %2};" : "=l"(r) : "f"(x), "f"(y));
    return r;
}
__device__ __forceinline__ void unpack2(unsigned long long v, float& x, float& y) {
    asm("mov.b64 {%0, %1}, %2;" : "=f"(x), "=f"(y) : "l"(v));
}

// ---------------- K0: zero the small per-launch state ---------------------
__global__ void zero_kernel() {
    int tid    = blockIdx.x * blockDim.x + threadIdx.x;
    int stride = gridDim.x * blockDim.x;
    for (int i = tid; i < SCAN_N; i += stride) g_count[i] = 0;
    for (int i = tid; i < BN;     i += stride) g_att_sum[i] = 0.f;
}

// ---------------- K1: fold Wa into the projection weights -----------------
__global__ void prep_kernel(const float* __restrict__ Wq, const float* __restrict__ Wk,
                            const float* __restrict__ Wew,
                            const float* __restrict__ bq, const float* __restrict__ bk,
                            const float* __restrict__ bew,
                            const float* __restrict__ Wa) {
    int i = threadIdx.x;
    float s1 = 0.f, s2 = 0.f;
    #pragma unroll 8
    for (int j = 0; j < D_MODEL; j++) {
        float w = Wa[j];
        s1 += Wq[i * D_MODEL + j] * w;
        s2 += Wk[i * D_MODEL + j] * w;
    }
    g_wqa[i] = s1;
    g_wka[i] = s2;
    if (i < D_EDGE) {
        float s3 = 0.f;
        #pragma unroll 8
        for (int j = 0; j < D_MODEL; j++) s3 += Wew[i * D_MODEL + j] * Wa[j];
        g_wewa[i] = s3;
    }
    if (i == 0) {
        float c = 0.f;
        for (int j = 0; j < D_MODEL; j++) c += (bq[j] + bk[j] + bew[j]) * Wa[j];
        g_cb = c;
    }
}

// ---------------- K2: per-node attention scalars qa, ka -------------------
__global__ void node_dot_kernel(const float* __restrict__ x) {
    int warp = (blockIdx.x * blockDim.x + threadIdx.x) >> 5;
    int lane = threadIdx.x & 31;
    if (warp >= BN) return;
    float4 v = ((const float4*)(x + (size_t)warp * D_MODEL))[lane];
    float4 a = ((const float4*)g_wqa)[lane];
    float4 b = ((const float4*)g_wka)[lane];
    float s1 = v.x * a.x + v.y * a.y + v.z * a.z + v.w * a.w;
    float s2 = v.x * b.x + v.y * b.y + v.z * b.z + v.w * b.w;
    #pragma unroll
    for (int off = 16; off; off >>= 1) {
        s1 += __shfl_down_sync(0xffffffffu, s1, off);
        s2 += __shfl_down_sync(0xffffffffu, s2, off);
    }
    if (lane == 0) { g_qa[warp] = s1; g_ka[warp] = s2; }
}

// ---------------- K3a: streaming edge dot ----------------------------------
__global__ void edge_dot_kernel(const float* __restrict__ e_emb) {
    int warp = (blockIdx.x * blockDim.x + threadIdx.x) >> 5;
    int lane = threadIdx.x & 31;
    int e    = warp * 2 + (lane >> 4);
    int l16  = lane & 15;
    if (e >= NE) return;
    float4 v = ((const float4*)e_emb)[(size_t)e * (D_EDGE / 4) + l16];
    float4 w = ((const float4*)g_wewa)[l16];
    float s = v.x * w.x + v.y * w.y + v.z * w.z + v.w * w.w;
    #pragma unroll
    for (int off = 8; off; off >>= 1) s += __shfl_down_sync(0xffffffffu, s, off, 16);
    if (l16 == 0) g_edot[e] = s;
}

// ---------------- K3b: logits + exp segment-sum + degree histogram --------
__global__ void edge_logit_kernel(const int* __restrict__ ei,
                                  const int* __restrict__ bi) {
    int e = blockIdx.x * blockDim.x + threadIdx.x;
    if (e >= NE) return;
    int src = clampi(ei[e],      NN - 1);
    int dst = clampi(ei[NE + e], NN - 1);
    int b   = clampi(bi[e],      NB - 1);
    int g   = b * NN + dst;
    float logit = (g_qa[b * NN + src] + g_ka[g] + g_edot[e] + g_cb) * 0.25f;
    float ex = expf(logit);
    g_att_exp[e] = ex;
    atomicAdd(&g_att_sum[g], ex);
    g_rank[e] = atomicAdd(&g_count[b * NN + src], 1);
}

// ---------------- scan: exclusive prefix over g_count ---------------------
__global__ void scan1_kernel() {   // 196 blocks x 256 threads, 1024 elems/block
    int b = blockIdx.x, t = threadIdx.x;
    int base = b * 1024 + t * 4;
    int4 c = *(const int4*)&g_count[base];
    int s0 = c.x, s1 = s0 + c.y, s2 = s1 + c.z, s3 = s2 + c.w;
    int tsum = s3;
    int lane = t & 31, wid = t >> 5;
    int v = tsum;
    #pragma unroll
    for (int o = 1; o < 32; o <<= 1) {
        int n = __shfl_up_sync(0xffffffffu, v, o);
        if (lane >= o) v += n;
    }
    __shared__ int wsum[8];
    if (lane == 31) wsum[wid] = v;
    __syncthreads();
    if (wid == 0) {
        int w = (lane < 8) ? wsum[lane] : 0;
        #pragma unroll
        for (int o = 1; o < 8; o <<= 1) {
            int n = __shfl_up_sync(0xffffffffu, w, o);
            if (lane >= o) w += n;
        }
        if (lane < 8) wsum[lane] = w;
    }
    __syncthreads();
    int excl = v - tsum + (wid ? wsum[wid - 1] : 0);
    g_off[base + 0] = excl;
    g_off[base + 1] = excl + s0;
    g_off[base + 2] = excl + s1;
    g_off[base + 3] = excl + s2;
    if (t == 255) g_bsum[b] = excl + s3;
}

__global__ void scan2_kernel() {   // 1 block x 256 threads over 196 block sums
    int t = threadIdx.x;
    int val = (t < SCAN_B) ? g_bsum[t] : 0;
    int lane = t & 31, wid = t >> 5;
    int v = val;
    #pragma unroll
    for (int o = 1; o < 32; o <<= 1) {
        int n = __shfl_up_sync(0xffffffffu, v, o);
        if (lane >= o) v += n;
    }
    __shared__ int wsum[8];
    if (lane == 31) wsum[wid] = v;
    __syncthreads();
    if (wid == 0) {
        int w = (lane < 8) ? wsum[lane] : 0;
        #pragma unroll
        for (int o = 1; o < 8; o <<= 1) {
            int n = __shfl_up_sync(0xffffffffu, w, o);
            if (lane >= o) w += n;
        }
        if (lane < 8) wsum[lane] = w;
    }
    __syncthreads();
    g_boff[t] = v - val + (wid ? wsum[wid - 1] : 0);   // exclusive
}

__global__ void scan3_kernel() {   // add block offsets
    int i = blockIdx.x * blockDim.x + threadIdx.x;
    if (i < SCAN_N) g_off[i] += g_boff[i >> 10];
}

// ---------------- K3c: reorder edges by (b,src); compute alpha ------------
__global__ void reorder_kernel(const int* __restrict__ ei,
                               const int* __restrict__ bi) {
    int e = blockIdx.x * blockDim.x + threadIdx.x;
    if (e >= NE) return;
    int src = clampi(ei[e],      NN - 1);
    int dst = clampi(ei[NE + e], NN - 1);
    int b   = clampi(bi[e],      NB - 1);
    int g   = b * NN + dst;
    float alpha = g_att_exp[e] / (g_att_sum[g] + 1e-9f);
    int p = g_off[b * NN + src] + g_rank[e];
    g_s_dst[p]   = g;
    g_s_eid[p]   = e;
    g_s_alpha[p] = alpha;
}

// ---------------- K4: gather (warp per node, no atomics) -------------------
__global__ void gather_kernel(const float* __restrict__ x,
                              const float* __restrict__ e_emb) {
    int n    = (blockIdx.x * blockDim.x + threadIdx.x) >> 5;
    int lane = threadIdx.x & 31;
    if (n >= BN) return;
    int beg = g_off[n], end = g_off[n + 1];

    float4 accX = make_float4(0.f, 0.f, 0.f, 0.f);
    float4 accE = make_float4(0.f, 0.f, 0.f, 0.f);
    float  aS = 0.f;
    for (int j = beg; j < end; j++) {
        int   dst = g_s_dst[j];          // uniform per warp (broadcast)
        int   eid = g_s_eid[j];
        float a   = g_s_alpha[j];
        float4 xv = ((const float4*)x)[(size_t)dst * (D_MODEL / 4) + lane];
        accX.x += a * xv.x; accX.y += a * xv.y;
        accX.z += a * xv.z; accX.w += a * xv.w;
        if (lane < 16) {
            float4 ev = ((const float4*)e_emb)[(size_t)eid * (D_EDGE / 4) + lane];
            accE.x += a * ev.x; accE.y += a * ev.y;
            accE.z += a * ev.z; accE.w += a * ev.w;
        }
        aS += a;
    }
    ((float4*)g_aggX)[(size_t)n * (D_MODEL / 4) + lane] = accX;
    if (lane < 16)
        ((float4*)g_aggE)[(size_t)n * (D_EDGE / 4) + lane] = accE;
    if (lane == 16) g_alphaSum[n] = aS;
    else if (lane == 17 && end <= beg) g_alphaSum[n] = 0.f;  // (aS==0 covers it; keep single path)
}

// ---------------- K5: fused output GEMM  out = [aggX|aggE]@[Wv;Wev] + as*(bv+bev)
#define TM 128
#define TN 128
#define TK 8
__global__ __launch_bounds__(256) void out_gemm_kernel(
        const float* __restrict__ Wv, const float* __restrict__ Wev,
        const float* __restrict__ bv, const float* __restrict__ bev,
        float* __restrict__ out) {
    __shared__ __align__(16) float As[TK][TM];
    __shared__ __align__(16) float Bs[TK][TN];
    int m0  = blockIdx.x * TM;
    int tid = threadIdx.x;
    int tr  = (tid >> 4) << 3;
    int tc  = (tid & 15) << 3;

    unsigned long long acc2[8][4];
    #pragma unroll
    for (int i = 0; i < 8; i++)
        #pragma unroll
        for (int j = 0; j < 4; j++) acc2[i][j] = 0ull;

    for (int k0 = 0; k0 < (D_MODEL + D_EDGE); k0 += TK) {
        {
            int r  = tid >> 1;
            int kk = (tid & 1) << 2;
            int k  = k0 + kk;
            size_t m = (size_t)(m0 + r);
            float4 av;
            if (k < D_MODEL) av = *(const float4*)(g_aggX + m * D_MODEL + k);
            else             av = *(const float4*)(g_aggE + m * D_EDGE + (k - D_MODEL));
            As[kk + 0][r] = av.x;
            As[kk + 1][r] = av.y;
            As[kk + 2][r] = av.z;
            As[kk + 3][r] = av.w;
        }
        {
            int kk = tid >> 5;
            int c  = (tid & 31) << 2;
            int kb = k0 + kk;
            float4 bvv;
            if (kb < D_MODEL) bvv = *(const float4*)(Wv  + (size_t)kb * D_MODEL + c);
            else              bvv = *(const float4*)(Wev + (size_t)(kb - D_MODEL) * D_MODEL + c);
            *(float4*)&Bs[kk][c] = bvv;
        }
        __syncthreads();
        #pragma unroll
        for (int kk = 0; kk < TK; kk++) {
            float4 a0 = *(const float4*)&As[kk][tr];
            float4 a1 = *(const float4*)&As[kk][tr + 4];
            ulonglong2 b0 = *(const ulonglong2*)&Bs[kk][tc];
            ulonglong2 b1 = *(const ulonglong2*)&Bs[kk][tc + 4];
            unsigned long long bb[4] = {b0.x, b0.y, b1.x, b1.y};
            float aa[8] = {a0.x, a0.y, a0.z, a0.w, a1.x, a1.y, a1.z, a1.w};
            #pragma unroll
            for (int i = 0; i < 8; i++) {
                unsigned long long ap = pack2(aa[i], aa[i]);
                #pragma unroll
                for (int j = 0; j < 4; j++) fma2(acc2[i][j], ap, bb[j]);
            }
        }
        __syncthreads();
    }

    float bias[8];
    #pragma unroll
    for (int j = 0; j < 8; j++) bias[j] = bv[tc + j] + bev[tc + j];
    #pragma unroll
    for (int i = 0; i < 8; i++) {
        int m = m0 + tr + i;
        if (m < BN) {
            float as = g_alphaSum[m];
            float o[8];
            #pragma unroll
            for (int j = 0; j < 4; j++) unpack2(acc2[i][j], o[2 * j], o[2 * j + 1]);
            #pragma unroll
            for (int j = 0; j < 8; j++) o[j] += as * bias[j];
            *(float4*)&out[(size_t)m * D_MODEL + tc]     = make_float4(o[0], o[1], o[2], o[3]);
            *(float4*)&out[(size_t)m * D_MODEL + tc + 4] = make_float4(o[4], o[5], o[6], o[7]);
        }
    }
}

// ---------------- launch ---------------------------------------------------
extern "C" void kernel_launch(void* const* d_in, const int* in_sizes, int n_in,
                              void* d_out, int out_size) {
    const float* x     = (const float*)d_in[0];
    const int*   ei    = (const int*)d_in[1];
    const float* e_emb = (const float*)d_in[2];
    const int*   bi    = (const int*)d_in[3];

    int o = 4;
    if (n_in >= 16 && in_sizes[4] == 1) { o = 5; }

    const float* Wq  = (const float*)d_in[o + 0];
    const float* bq  = (const float*)d_in[o + 1];
    const float* Wk  = (const float*)d_in[o + 2];
    const float* bk  = (const float*)d_in[o + 3];
    const float* Wv  = (const float*)d_in[o + 4];
    const float* bv  = (const float*)d_in[o + 5];
    const float* Wew = (const float*)d_in[o + 6];
    const float* bew = (const float*)d_in[o + 7];
    const float* Wev = (const float*)d_in[o + 8];
    const float* bev = (const float*)d_in[o + 9];
    const float* Wa  = (const float*)d_in[o + 10];
    float* out = (float*)d_out;

    zero_kernel<<<512, 256>>>();
    prep_kernel<<<1, 128>>>(Wq, Wk, Wew, bq, bk, bew, Wa);
    node_dot_kernel<<<(BN * 32 + 255) / 256, 256>>>(x);
    edge_dot_kernel<<<(NE * 16 + 255) / 256, 256>>>(e_emb);
    edge_logit_kernel<<<(NE + 255) / 256, 256>>>(ei, bi);
    scan1_kernel<<<SCAN_B, 256>>>();
    scan2_kernel<<<1, 256>>>();
    scan3_kernel<<<(SCAN_N + 255) / 256, 256>>>();
    reorder_kernel<<<(NE + 255) / 256, 256>>>(ei, bi);
    gather_kernel<<<(BN * 32 + 255) / 256, 256>>>(x, e_emb);
    out_gemm_kernel<<<BNP / TM, 256>>>(Wv, Wev, bv, bev, out);
}